// round 1
// baseline (speedup 1.0000x reference)
#include <cuda_runtime.h>
#include <cstdint>

// vanillaMLP fused kernel: hash-grid encode (4 live levels) -> 8->64->16 MLP
// -> trunc_exp sigma -> analytic backward d sigma / d x_norm -> normals.
//
// Outputs concatenated: sigma[N], fea[N,16], normals[N,3], grad[N,3]  (23N floats)

#define T_SIZE  524288          // 1 << 19
#define T_MASK  (T_SIZE - 1)
#define NLIVE   4               // CURRENT_LEVEL = 4 -> first 8 features live
#define DENSITY_BIAS (-1.0f)
#define CLAMP_MAX 10.0f

__global__ void __launch_bounds__(256, 2)
nerf_fused_kernel(const float* __restrict__ pts,
                  const float* __restrict__ table,
                  const float* __restrict__ W1,
                  const float* __restrict__ W2,
                  float* __restrict__ out,
                  int n)
{
    // Stage weights in shared: W1 first-8 columns [64][8], full W2 [16][64]
    __shared__ float w1s[64 * 8];
    __shared__ float w2s[16 * 64];
    {
        int tid = threadIdx.x;
        for (int i = tid; i < 64 * 8; i += 256) {
            int j = i >> 3, k = i & 7;
            w1s[i] = W1[j * 32 + k];
        }
        for (int i = tid; i < 16 * 64; i += 256) w2s[i] = W2[i];
        __syncthreads();
    }

    int pid = blockIdx.x * 256 + threadIdx.x;
    if (pid >= n) return;

    // normalize to [0,1] exactly like reference: (p + 1) * 0.5
    float x = (pts[pid * 3 + 0] + 1.0f) * 0.5f;
    float y = (pts[pid * 3 + 1] + 1.0f) * 0.5f;
    float z = (pts[pid * 3 + 2] + 1.0f) * 0.5f;

    const float RES[NLIVE] = {16.0f, 22.0f, 30.0f, 42.0f};

    float feat[8];
    float2 tv[NLIVE][8];        // gathered table values, kept for backward
    float fr[NLIVE][3];         // fractional coords, kept for backward

    #pragma unroll
    for (int l = 0; l < NLIVE; l++) {
        float res = RES[l];
        float fx = x * res, fy = y * res, fz = z * res;
        float x0 = floorf(fx), y0 = floorf(fy), z0 = floorf(fz);
        float frx = fx - x0, fry = fy - y0, frz = fz - z0;
        fr[l][0] = frx; fr[l][1] = fry; fr[l][2] = frz;
        unsigned ux = (unsigned)(int)x0;
        unsigned uy = (unsigned)(int)y0;
        unsigned uz = (unsigned)(int)z0;

        float f0 = 0.0f, f1 = 0.0f;
        #pragma unroll
        for (int c = 0; c < 8; c++) {
            unsigned ox = (c >> 2) & 1u, oy = (c >> 1) & 1u, oz = c & 1u;
            unsigned h = (ux + ox) * 1u
                       ^ (uy + oy) * 2654435761u
                       ^ (uz + oz) * 805459861u;
            unsigned idx = h & T_MASK;
            float2 t = __ldg(((const float2*)table) + (size_t)l * T_SIZE + idx);
            tv[l][c] = t;
            float wx = ox ? frx : 1.0f - frx;
            float wy = oy ? fry : 1.0f - fry;
            float wz = oz ? frz : 1.0f - frz;
            float w = wx * wy * wz;
            f0 = fmaf(w, t.x, f0);
            f1 = fmaf(w, t.y, f1);
        }
        feat[2 * l]     = f0;
        feat[2 * l + 1] = f1;
    }

    // ---- fused MLP forward + backward-prep ----
    // h_j = relu(sum_k feat[k] * W1[j,k])
    // fea_i = sum_j h_j * W2[i,j]
    // dacc_k = sum_j (h_j>0) * W2[0,j] * W1[j,k]   (grad of fea0 wrt feat, pre-g)
    float fea[16];
    float dacc[8];
    #pragma unroll
    for (int i = 0; i < 16; i++) fea[i] = 0.0f;
    #pragma unroll
    for (int k = 0; k < 8; k++) dacc[k] = 0.0f;

    #pragma unroll 4
    for (int j = 0; j < 64; j++) {
        float hj = 0.0f;
        #pragma unroll
        for (int k = 0; k < 8; k++) hj = fmaf(feat[k], w1s[j * 8 + k], hj);
        float hp = fmaxf(hj, 0.0f);
        #pragma unroll
        for (int i = 0; i < 16; i++) fea[i] = fmaf(hp, w2s[i * 64 + j], fea[i]);
        float cm = (hj > 0.0f) ? w2s[j] : 0.0f;   // W2 row 0 gated by relu mask
        #pragma unroll
        for (int k = 0; k < 8; k++) dacc[k] = fmaf(cm, w1s[j * 8 + k], dacc[k]);
    }

    float pre   = fea[0] + DENSITY_BIAS;
    float sigma = __expf(pre) ;
    // exact exp to match reference within fp32: use expf (not fast approx)
    sigma = expf(pre);
    float g = expf(fminf(pre, CLAMP_MAX));

    // ---- hash-grid backward: grad of sigma wrt normalized x ----
    float gx = 0.0f, gy = 0.0f, gz = 0.0f;
    #pragma unroll
    for (int l = 0; l < NLIVE; l++) {
        float res = RES[l];
        float df0 = g * dacc[2 * l];
        float df1 = g * dacc[2 * l + 1];
        float frx = fr[l][0], fry = fr[l][1], frz = fr[l][2];
        float ax = 0.0f, ay = 0.0f, az = 0.0f;
        #pragma unroll
        for (int c = 0; c < 8; c++) {
            int ox = (c >> 2) & 1, oy = (c >> 1) & 1, oz = c & 1;
            float2 t = tv[l][c];
            float tdot = fmaf(df0, t.x, df1 * t.y);
            float wx = ox ? frx : 1.0f - frx;
            float wy = oy ? fry : 1.0f - fry;
            float wz = oz ? frz : 1.0f - frz;
            float sx = ox ? 1.0f : -1.0f;
            float sy = oy ? 1.0f : -1.0f;
            float sz = oz ? 1.0f : -1.0f;
            ax = fmaf(tdot, sx * (wy * wz), ax);
            ay = fmaf(tdot, sy * (wx * wz), ay);
            az = fmaf(tdot, sz * (wx * wy), az);
        }
        gx = fmaf(res, ax, gx);
        gy = fmaf(res, ay, gy);
        gz = fmaf(res, az, gz);
    }

    float nrm = sqrtf(fmaf(gx, gx, fmaf(gy, gy, gz * gz)));
    float inv = 1.0f / nrm;

    // ---- outputs: [sigma | fea | normals | grad] ----
    out[pid] = sigma;

    float4* feaOut = (float4*)(out + (size_t)n) + pid * 4;
    feaOut[0] = make_float4(fea[0],  fea[1],  fea[2],  fea[3]);
    feaOut[1] = make_float4(fea[4],  fea[5],  fea[6],  fea[7]);
    feaOut[2] = make_float4(fea[8],  fea[9],  fea[10], fea[11]);
    feaOut[3] = make_float4(fea[12], fea[13], fea[14], fea[15]);

    float* nOut = out + (size_t)n * 17 + pid * 3;
    nOut[0] = gx * inv; nOut[1] = gy * inv; nOut[2] = gz * inv;

    float* gOut = out + (size_t)n * 20 + pid * 3;
    gOut[0] = gx; gOut[1] = gy; gOut[2] = gz;
}

extern "C" void kernel_launch(void* const* d_in, const int* in_sizes, int n_in,
                              void* d_out, int out_size)
{
    const float* pts   = (const float*)d_in[0];
    const float* table = (const float*)d_in[1];
    const float* W1    = (const float*)d_in[2];
    const float* W2    = (const float*)d_in[3];
    float* out = (float*)d_out;
    int n = in_sizes[0] / 3;
    int blocks = (n + 255) / 256;
    nerf_fused_kernel<<<blocks, 256>>>(pts, table, W1, W2, out, n);
}

// round 2
// speedup vs baseline: 1.2015x; 1.2015x over previous
#include <cuda_runtime.h>
#include <cstdint>

// vanillaMLP fused: hash-grid encode (4 live levels, rest masked to 0)
// -> 8->64->16 MLP -> trunc_exp sigma -> analytic d sigma/d x_norm -> normals.
// Backward restructured: per-level derivative partial sums accumulated in the
// forward corner loop (linear in df), so no gathered values are kept live.
// Outputs: [sigma N | fea N*16 | normals N*3 | grad N*3]

#define T_SIZE  524288          // 1 << 19
#define T_MASK  (T_SIZE - 1)
#define NLIVE   4
#define DENSITY_BIAS (-1.0f)
#define CLAMP_MAX 10.0f

__global__ void __launch_bounds__(128, 6)
nerf_fused_kernel(const float* __restrict__ pts,
                  const float* __restrict__ table,
                  const float* __restrict__ W1,
                  const float* __restrict__ W2,
                  float* __restrict__ out,
                  int n)
{
    __shared__ float  w1s[64 * 8];
    __shared__ float  w2s[16 * 64];
    __shared__ float4 stage[128 * 4];          // 8KB staging for coalesced stores

    const int tid = threadIdx.x;
    for (int i = tid; i < 64 * 8; i += 128) {
        int j = i >> 3, k = i & 7;
        w1s[i] = W1[j * 32 + k];
    }
    for (int i = tid; i < 16 * 64; i += 128) w2s[i] = W2[i];
    __syncthreads();

    const int pid    = blockIdx.x * 128 + tid;
    const bool active = (pid < n);
    const int  rp     = active ? pid : 0;

    float x = (pts[rp * 3 + 0] + 1.0f) * 0.5f;
    float y = (pts[rp * 3 + 1] + 1.0f) * 0.5f;
    float z = (pts[rp * 3 + 2] + 1.0f) * 0.5f;

    const float RES[NLIVE] = {16.0f, 22.0f, 30.0f, 42.0f};

    float feat[8];
    float acc[NLIVE][6];        // per level: ax0,ax1, ay0,ay1, az0,az1

    #pragma unroll
    for (int l = 0; l < NLIVE; l++) {
        const float res = RES[l];
        float fx = x * res, fy = y * res, fz = z * res;
        float x0 = floorf(fx), y0 = floorf(fy), z0 = floorf(fz);
        float frx = fx - x0, fry = fy - y0, frz = fz - z0;
        float mfx = 1.0f - frx, mfy = 1.0f - fry, mfz = 1.0f - frz;
        unsigned ux = (unsigned)(int)x0;
        unsigned uy = (unsigned)(int)y0;
        unsigned uz = (unsigned)(int)z0;

        const float2* __restrict__ tbl = ((const float2*)table) + (size_t)l * T_SIZE;

        float f0 = 0.0f, f1 = 0.0f;
        float ax0 = 0.f, ax1 = 0.f, ay0 = 0.f, ay1 = 0.f, az0 = 0.f, az1 = 0.f;

        #pragma unroll
        for (int c = 0; c < 8; c++) {
            const unsigned ox = (c >> 2) & 1u, oy = (c >> 1) & 1u, oz = c & 1u;
            unsigned h = (ux + ox)
                       ^ (uy + oy) * 2654435761u
                       ^ (uz + oz) * 805459861u;
            float2 t = __ldg(tbl + (h & T_MASK));

            float wx = ox ? frx : mfx;
            float wy = oy ? fry : mfy;
            float wz = oz ? frz : mfz;
            float myz = wy * wz;               // |d w / d x|
            float mxz = wx * wz;               // |d w / d y|
            float mxy = wx * wy;               // |d w / d z|
            float w   = wx * myz;

            f0 = fmaf(w, t.x, f0);
            f1 = fmaf(w, t.y, f1);
            // signed derivative partial sums (sign = +1 if offset bit set)
            float sx = ox ? myz : -myz;
            float sy = oy ? mxz : -mxz;
            float sz = oz ? mxy : -mxy;
            ax0 = fmaf(sx, t.x, ax0);  ax1 = fmaf(sx, t.y, ax1);
            ay0 = fmaf(sy, t.x, ay0);  ay1 = fmaf(sy, t.y, ay1);
            az0 = fmaf(sz, t.x, az0);  az1 = fmaf(sz, t.y, az1);
        }
        feat[2 * l]     = f0;
        feat[2 * l + 1] = f1;
        acc[l][0] = ax0; acc[l][1] = ax1;
        acc[l][2] = ay0; acc[l][3] = ay1;
        acc[l][4] = az0; acc[l][5] = az1;
    }

    // ---- fused MLP forward + backward-prep ----
    float fea[16];
    float dacc[8];
    #pragma unroll
    for (int i = 0; i < 16; i++) fea[i] = 0.0f;
    #pragma unroll
    for (int k = 0; k < 8; k++) dacc[k] = 0.0f;

    #pragma unroll 4
    for (int j = 0; j < 64; j++) {
        float hj = 0.0f;
        #pragma unroll
        for (int k = 0; k < 8; k++) hj = fmaf(feat[k], w1s[j * 8 + k], hj);
        float hp = fmaxf(hj, 0.0f);
        #pragma unroll
        for (int i = 0; i < 16; i++) fea[i] = fmaf(hp, w2s[i * 64 + j], fea[i]);
        float cm = (hj > 0.0f) ? w2s[j] : 0.0f;
        #pragma unroll
        for (int k = 0; k < 8; k++) dacc[k] = fmaf(cm, w1s[j * 8 + k], dacc[k]);
    }

    float pre   = fea[0] + DENSITY_BIAS;
    float sigma = expf(pre);
    float g     = expf(fminf(pre, CLAMP_MAX));

    // ---- fold derivative partials ----
    float gx = 0.0f, gy = 0.0f, gz = 0.0f;
    #pragma unroll
    for (int l = 0; l < NLIVE; l++) {
        float d0 = dacc[2 * l], d1 = dacc[2 * l + 1];
        gx = fmaf(RES[l], fmaf(d0, acc[l][0], d1 * acc[l][1]), gx);
        gy = fmaf(RES[l], fmaf(d0, acc[l][2], d1 * acc[l][3]), gy);
        gz = fmaf(RES[l], fmaf(d0, acc[l][4], d1 * acc[l][5]), gz);
    }
    gx *= g; gy *= g; gz *= g;

    float nrm = sqrtf(fmaf(gx, gx, fmaf(gy, gy, gz * gz)));
    float inv = 1.0f / nrm;

    // ---- coalesced outputs via shared staging ----
    if (active) out[pid] = sigma;

    const int npts = min(128, n - blockIdx.x * 128);

    // fea: stage [128][4] float4, then contiguous block store
    stage[tid * 4 + 0] = make_float4(fea[0],  fea[1],  fea[2],  fea[3]);
    stage[tid * 4 + 1] = make_float4(fea[4],  fea[5],  fea[6],  fea[7]);
    stage[tid * 4 + 2] = make_float4(fea[8],  fea[9],  fea[10], fea[11]);
    stage[tid * 4 + 3] = make_float4(fea[12], fea[13], fea[14], fea[15]);
    __syncthreads();
    {
        float4* dst = (float4*)(out + (size_t)n) + (size_t)blockIdx.x * 512;
        int lim = npts * 4;
        for (int i = tid; i < lim; i += 128) dst[i] = stage[i];
    }
    __syncthreads();

    // normals + grad: 6 floats per point in same buffer
    {
        float* sf = (float*)stage;
        sf[tid * 6 + 0] = gx * inv;
        sf[tid * 6 + 1] = gy * inv;
        sf[tid * 6 + 2] = gz * inv;
        sf[tid * 6 + 3] = gx;
        sf[tid * 6 + 4] = gy;
        sf[tid * 6 + 5] = gz;
        __syncthreads();
        float* ndst = out + (size_t)n * 17 + (size_t)blockIdx.x * 384;
        float* gdst = out + (size_t)n * 20 + (size_t)blockIdx.x * 384;
        int lim = npts * 3;
        for (int i = tid; i < lim; i += 128) {
            int p = i / 3, c = i - p * 3;
            ndst[i] = sf[p * 6 + c];
        }
        for (int i = tid; i < lim; i += 128) {
            int p = i / 3, c = i - p * 3;
            gdst[i] = sf[p * 6 + 3 + c];
        }
    }
}

extern "C" void kernel_launch(void* const* d_in, const int* in_sizes, int n_in,
                              void* d_out, int out_size)
{
    const float* pts   = (const float*)d_in[0];
    const float* table = (const float*)d_in[1];
    const float* W1    = (const float*)d_in[2];
    const float* W2    = (const float*)d_in[3];
    float* out = (float*)d_out;
    int n = in_sizes[0] / 3;
    int blocks = (n + 127) / 128;
    nerf_fused_kernel<<<blocks, 128>>>(pts, table, W1, W2, out, n);
}

// round 3
// speedup vs baseline: 1.3272x; 1.1046x over previous
#include <cuda_runtime.h>
#include <cstdint>

// vanillaMLP fused: hash-grid encode (4 live levels) -> 8->64->16 MLP
// -> trunc_exp sigma -> analytic d sigma/d x_norm -> normals.
// Round 3: f32x2 packed FMA throughout, vectorized LDS (float4) with
// transposed W2 staging, strength-reduced hash, coalesced pts load.
// Outputs: [sigma N | fea N*16 | normals N*3 | grad N*3]

#define T_SIZE  524288          // 1 << 19
#define T_MASK  (T_SIZE - 1)
#define NLIVE   4
#define DENSITY_BIAS (-1.0f)
#define CLAMP_MAX 10.0f

typedef unsigned long long u64;

__device__ __forceinline__ u64 pk(float a, float b) {
    u64 r; asm("mov.b64 %0, {%1,%2};" : "=l"(r) : "f"(a), "f"(b)); return r;
}
__device__ __forceinline__ u64 pk2(float a) { return pk(a, a); }
__device__ __forceinline__ float2 upk(u64 v) {
    float2 r; asm("mov.b64 {%0,%1}, %2;" : "=f"(r.x), "=f"(r.y) : "l"(v)); return r;
}
__device__ __forceinline__ u64 fma2(u64 a, u64 b, u64 c) {
    u64 d; asm("fma.rn.f32x2 %0, %1, %2, %3;" : "=l"(d) : "l"(a), "l"(b), "l"(c)); return d;
}
__device__ __forceinline__ u64 mul2(u64 a, u64 b) {
    u64 d; asm("mul.rn.f32x2 %0, %1, %2;" : "=l"(d) : "l"(a), "l"(b)); return d;
}

__global__ void __launch_bounds__(128, 6)
nerf_fused_kernel(const float* __restrict__ pts,
                  const float* __restrict__ table,
                  const float* __restrict__ W1,
                  const float* __restrict__ W2,
                  float* __restrict__ out,
                  int n)
{
    __shared__ float4 w1f4[64 * 2];    // W1 rows, first 8 cols: [j][0..7]
    __shared__ float4 w2f4[64 * 4];    // W2 transposed: row j holds W2[0..15][j]
    __shared__ float4 stage[128 * 4];  // 8KB staging (pts in, outputs out)

    const int tid = threadIdx.x;
    {
        float* w1s = (float*)w1f4;
        for (int i = tid; i < 64 * 8; i += 128) {
            int j = i >> 3, k = i & 7;
            w1s[i] = W1[j * 32 + k];
        }
        float* w2s = (float*)w2f4;
        for (int i = tid; i < 64 * 16; i += 128) {
            int j = i >> 4, k = i & 15;            // w2t[j][k] = W2[k][j]
            w2s[i] = W2[k * 64 + j];
        }
    }

    // coalesced point load through shared
    float* sf = (float*)stage;
    {
        size_t base = (size_t)blockIdx.x * 384;
        size_t lim3 = (size_t)n * 3;
        for (int i = tid; i < 384; i += 128) {
            size_t gi = base + i;
            sf[i] = (gi < lim3) ? pts[gi] : 0.0f;
        }
    }
    __syncthreads();

    const int pid = blockIdx.x * 128 + tid;
    const bool active = (pid < n);

    float x = (sf[tid * 3 + 0] + 1.0f) * 0.5f;
    float y = (sf[tid * 3 + 1] + 1.0f) * 0.5f;
    float z = (sf[tid * 3 + 2] + 1.0f) * 0.5f;
    __syncthreads();   // stage reused for outputs later

    const float RES[NLIVE] = {16.0f, 22.0f, 30.0f, 42.0f};

    u64 feat2[NLIVE];          // (feat[2l], feat[2l+1])
    u64 accx[NLIVE], accy[NLIVE], accz[NLIVE];

    #pragma unroll
    for (int l = 0; l < NLIVE; l++) {
        const float res = RES[l];
        float fx = x * res, fy = y * res, fz = z * res;
        float x0 = floorf(fx), y0 = floorf(fy), z0 = floorf(fz);
        float frx = fx - x0, fry = fy - y0, frz = fz - z0;
        float mfx = 1.0f - frx, mfy = 1.0f - fry, mfz = 1.0f - frz;
        unsigned ux = (unsigned)(int)x0;
        unsigned uy = (unsigned)(int)y0;
        unsigned uz = (unsigned)(int)z0;
        // strength-reduced hash components
        unsigned hx0 = ux,                  hx1 = ux + 1u;
        unsigned hy0 = uy * 2654435761u,    hy1 = hy0 + 2654435761u;
        unsigned hz0 = uz * 805459861u,     hz1 = hz0 + 805459861u;

        const float2* __restrict__ tbl = ((const float2*)table) + (size_t)l * T_SIZE;

        u64 f01 = 0, ax = 0, ay = 0, az = 0;

        #pragma unroll
        for (int c = 0; c < 8; c++) {
            const int ox = (c >> 2) & 1, oy = (c >> 1) & 1, oz = c & 1;
            unsigned h = (ox ? hx1 : hx0) ^ (oy ? hy1 : hy0) ^ (oz ? hz1 : hz0);
            float2 t = __ldg(tbl + (h & T_MASK));
            u64 t01 = pk(t.x, t.y);

            float wx = ox ? frx : mfx;
            float wy = oy ? fry : mfy;
            float wz = oz ? frz : mfz;
            float myz = wy * wz;
            float mxz = wx * wz;
            float mxy = wx * wy;

            f01 = fma2(pk2(wx * myz), t01, f01);
            ax  = fma2(pk2(ox ?  myz : -myz), t01, ax);
            ay  = fma2(pk2(oy ?  mxz : -mxz), t01, ay);
            az  = fma2(pk2(oz ?  mxy : -mxy), t01, az);
        }
        feat2[l] = f01;
        accx[l] = ax; accy[l] = ay; accz[l] = az;
    }

    // ---- fused MLP forward + backward-prep (all f32x2) ----
    u64 fea2[8];
    u64 dacc2[NLIVE];
    #pragma unroll
    for (int i = 0; i < 8; i++) fea2[i] = 0;
    #pragma unroll
    for (int l = 0; l < NLIVE; l++) dacc2[l] = 0;

    #pragma unroll 4
    for (int j = 0; j < 64; j++) {
        float4 wa = w1f4[j * 2 + 0];
        float4 wb = w1f4[j * 2 + 1];
        u64 a0 = pk(wa.x, wa.y), a1 = pk(wa.z, wa.w);
        u64 a2 = pk(wb.x, wb.y), a3 = pk(wb.z, wb.w);

        u64 s = fma2(feat2[0], a0,
                fma2(feat2[1], a1,
                fma2(feat2[2], a2,
                mul2(feat2[3], a3))));
        float2 sp = upk(s);
        float hj = sp.x + sp.y;
        float hp = fmaxf(hj, 0.0f);
        u64 hp2 = pk2(hp);

        float4 c0 = w2f4[j * 4 + 0];
        float4 c1 = w2f4[j * 4 + 1];
        float4 c2 = w2f4[j * 4 + 2];
        float4 c3 = w2f4[j * 4 + 3];
        fea2[0] = fma2(hp2, pk(c0.x, c0.y), fea2[0]);
        fea2[1] = fma2(hp2, pk(c0.z, c0.w), fea2[1]);
        fea2[2] = fma2(hp2, pk(c1.x, c1.y), fea2[2]);
        fea2[3] = fma2(hp2, pk(c1.z, c1.w), fea2[3]);
        fea2[4] = fma2(hp2, pk(c2.x, c2.y), fea2[4]);
        fea2[5] = fma2(hp2, pk(c2.z, c2.w), fea2[5]);
        fea2[6] = fma2(hp2, pk(c3.x, c3.y), fea2[6]);
        fea2[7] = fma2(hp2, pk(c3.z, c3.w), fea2[7]);

        float cm = (hj > 0.0f) ? c0.x : 0.0f;   // W2[0][j] gated by relu mask
        u64 cm2 = pk2(cm);
        dacc2[0] = fma2(cm2, a0, dacc2[0]);
        dacc2[1] = fma2(cm2, a1, dacc2[1]);
        dacc2[2] = fma2(cm2, a2, dacc2[2]);
        dacc2[3] = fma2(cm2, a3, dacc2[3]);
    }

    float2 fea01 = upk(fea2[0]);
    float pre   = fea01.x + DENSITY_BIAS;
    float sigma = expf(pre);
    float g     = expf(fminf(pre, CLAMP_MAX));

    // ---- fold derivative partials ----
    float gx = 0.0f, gy = 0.0f, gz = 0.0f;
    #pragma unroll
    for (int l = 0; l < NLIVE; l++) {
        float2 px = upk(mul2(dacc2[l], accx[l]));
        float2 py = upk(mul2(dacc2[l], accy[l]));
        float2 pz = upk(mul2(dacc2[l], accz[l]));
        gx = fmaf(RES[l], px.x + px.y, gx);
        gy = fmaf(RES[l], py.x + py.y, gy);
        gz = fmaf(RES[l], pz.x + pz.y, gz);
    }
    gx *= g; gy *= g; gz *= g;

    float nrm = sqrtf(fmaf(gx, gx, fmaf(gy, gy, gz * gz)));
    float inv = 1.0f / nrm;

    // ---- coalesced outputs via shared staging ----
    if (active) out[pid] = sigma;

    const int npts = min(128, n - blockIdx.x * 128);

    {
        float2 f0 = upk(fea2[0]), f1 = upk(fea2[1]);
        float2 f2 = upk(fea2[2]), f3 = upk(fea2[3]);
        float2 f4 = upk(fea2[4]), f5 = upk(fea2[5]);
        float2 f6 = upk(fea2[6]), f7 = upk(fea2[7]);
        stage[tid * 4 + 0] = make_float4(f0.x, f0.y, f1.x, f1.y);
        stage[tid * 4 + 1] = make_float4(f2.x, f2.y, f3.x, f3.y);
        stage[tid * 4 + 2] = make_float4(f4.x, f4.y, f5.x, f5.y);
        stage[tid * 4 + 3] = make_float4(f6.x, f6.y, f7.x, f7.y);
    }
    __syncthreads();
    {
        float4* dst = (float4*)(out + (size_t)n) + (size_t)blockIdx.x * 512;
        int lim = npts * 4;
        for (int i = tid; i < lim; i += 128) dst[i] = stage[i];
    }
    __syncthreads();

    // normals + grad: 6 floats per point in same buffer
    sf[tid * 6 + 0] = gx * inv;
    sf[tid * 6 + 1] = gy * inv;
    sf[tid * 6 + 2] = gz * inv;
    sf[tid * 6 + 3] = gx;
    sf[tid * 6 + 4] = gy;
    sf[tid * 6 + 5] = gz;
    __syncthreads();
    {
        float* ndst = out + (size_t)n * 17 + (size_t)blockIdx.x * 384;
        float* gdst = out + (size_t)n * 20 + (size_t)blockIdx.x * 384;
        int lim = npts * 3;
        for (int i = tid; i < lim; i += 128) {
            int p = i / 3, c = i - p * 3;
            ndst[i] = sf[p * 6 + c];
        }
        for (int i = tid; i < lim; i += 128) {
            int p = i / 3, c = i - p * 3;
            gdst[i] = sf[p * 6 + 3 + c];
        }
    }
}

extern "C" void kernel_launch(void* const* d_in, const int* in_sizes, int n_in,
                              void* d_out, int out_size)
{
    const float* pts   = (const float*)d_in[0];
    const float* table = (const float*)d_in[1];
    const float* W1    = (const float*)d_in[2];
    const float* W2    = (const float*)d_in[3];
    float* out = (float*)d_out;
    int n = in_sizes[0] / 3;
    int blocks = (n + 127) / 128;
    nerf_fused_kernel<<<blocks, 128>>>(pts, table, W1, W2, out, n);
}

// round 4
// speedup vs baseline: 1.4729x; 1.1098x over previous
#include <cuda_runtime.h>
#include <cstdint>

// vanillaMLP fused. Round 4: de-hash the 4 live levels into dense z-pair-packed
// grids (precompute kernel), so the hot kernel gathers 16 x LDG.128 instead of
// 32 x LDG.64 -> gather wavefronts halved. f32x2 MLP unchanged.
// Outputs: [sigma N | fea N*16 | normals N*3 | grad N*3]

#define T_SIZE  524288          // 1 << 19
#define T_MASK  (T_SIZE - 1)
#define DENSITY_BIAS (-1.0f)
#define CLAMP_MAX 10.0f
#define PRIME_Y 2654435761u
#define PRIME_Z 805459861u

// dense grids: dims (res+2)^3, cell (x,y,z) = float4(tbl[z], tbl[z+1])
// L0 res16 D18: 5832 | L1 res22 D24: 13824 | L2 res30 D32: 32768 | L3 res42 D44: 85184
#define D0 18
#define D1 24
#define D2 32
#define D3 44
#define OFF0 0
#define OFF1 5832
#define OFF2 19656
#define OFF3 52424
#define NDENSE 137608

__device__ float4 g_dense[NDENSE + 8];

typedef unsigned long long u64;

__device__ __forceinline__ u64 pk(float a, float b) {
    u64 r; asm("mov.b64 %0, {%1,%2};" : "=l"(r) : "f"(a), "f"(b)); return r;
}
__device__ __forceinline__ u64 pk2(float a) { return pk(a, a); }
__device__ __forceinline__ float2 upk(u64 v) {
    float2 r; asm("mov.b64 {%0,%1}, %2;" : "=f"(r.x), "=f"(r.y) : "l"(v)); return r;
}
__device__ __forceinline__ u64 fma2(u64 a, u64 b, u64 c) {
    u64 d; asm("fma.rn.f32x2 %0, %1, %2, %3;" : "=l"(d) : "l"(a), "l"(b), "l"(c)); return d;
}
__device__ __forceinline__ u64 mul2(u64 a, u64 b) {
    u64 d; asm("mul.rn.f32x2 %0, %1, %2;" : "=l"(d) : "l"(a), "l"(b)); return d;
}
__device__ __forceinline__ u64 add2(u64 a, u64 b) {
    u64 d; asm("add.rn.f32x2 %0, %1, %2;" : "=l"(d) : "l"(a), "l"(b)); return d;
}
__device__ __forceinline__ u64 neg2(u64 a) { return a ^ 0x8000000080000000ULL; }

__global__ void __launch_bounds__(256)
build_dense_kernel(const float* __restrict__ table)
{
    int i = blockIdx.x * 256 + threadIdx.x;
    if (i >= NDENSE) return;
    int l, local, D;
    if (i < OFF1)      { l = 0; local = i;        D = D0; }
    else if (i < OFF2) { l = 1; local = i - OFF1; D = D1; }
    else if (i < OFF3) { l = 2; local = i - OFF2; D = D2; }
    else               { l = 3; local = i - OFF3; D = D3; }
    int z = local % D;
    int t = local / D;
    int y = t % D;
    int x = t / D;
    unsigned hb = (unsigned)x ^ ((unsigned)y * PRIME_Y);
    unsigned h0 = hb ^ ((unsigned)z * PRIME_Z);
    unsigned h1 = hb ^ ((unsigned)(z + 1) * PRIME_Z);
    const float2* __restrict__ tbl = (const float2*)table + (size_t)l * T_SIZE;
    float2 a = __ldg(tbl + (h0 & T_MASK));
    float2 b = __ldg(tbl + (h1 & T_MASK));
    g_dense[i] = make_float4(a.x, a.y, b.x, b.y);
}

__global__ void __launch_bounds__(128, 6)
nerf_fused_kernel(const float* __restrict__ pts,
                  const float* __restrict__ W1,
                  const float* __restrict__ W2,
                  float* __restrict__ out,
                  int n)
{
    __shared__ float4 w1f4[64 * 2];    // W1 rows, first 8 cols
    __shared__ float4 w2f4[64 * 4];    // W2 transposed: row j holds W2[0..15][j]
    __shared__ float4 stage[128 * 4];  // 8KB staging (pts in, outputs out)

    const int tid = threadIdx.x;
    {
        float* w1s = (float*)w1f4;
        for (int i = tid; i < 64 * 8; i += 128) {
            int j = i >> 3, k = i & 7;
            w1s[i] = W1[j * 32 + k];
        }
        float* w2s = (float*)w2f4;
        for (int i = tid; i < 64 * 16; i += 128) {
            int j = i >> 4, k = i & 15;
            w2s[i] = W2[k * 64 + j];
        }
    }

    float* sf = (float*)stage;
    {
        size_t base = (size_t)blockIdx.x * 384;
        size_t lim3 = (size_t)n * 3;
        for (int i = tid; i < 384; i += 128) {
            size_t gi = base + i;
            sf[i] = (gi < lim3) ? pts[gi] : 0.0f;
        }
    }
    __syncthreads();

    const int pid = blockIdx.x * 128 + tid;
    const bool active = (pid < n);

    float x = (sf[tid * 3 + 0] + 1.0f) * 0.5f;
    float y = (sf[tid * 3 + 1] + 1.0f) * 0.5f;
    float z = (sf[tid * 3 + 2] + 1.0f) * 0.5f;
    __syncthreads();

    const float RES[4]  = {16.0f, 22.0f, 30.0f, 42.0f};
    const int   DIMS[4] = {D0, D1, D2, D3};
    const int   OFFS[4] = {OFF0, OFF1, OFF2, OFF3};

    u64 feat2[4];
    u64 accx[4], accy[4], accz[4];

    #pragma unroll
    for (int l = 0; l < 4; l++) {
        const float res = RES[l];
        const int   D   = DIMS[l];
        float fx = x * res, fy = y * res, fz = z * res;
        float x0 = floorf(fx), y0 = floorf(fy), z0 = floorf(fz);
        float frx = fx - x0, fry = fy - y0, frz = fz - z0;
        float mfx = 1.0f - frx, mfy = 1.0f - fry, mfz = 1.0f - frz;
        int xi = (int)x0, yi = (int)y0, zi = (int)z0;

        const float4* __restrict__ dl = g_dense + OFFS[l];
        int b00 = (xi * D + yi) * D + zi;
        float4 v00 = __ldg(dl + b00);
        float4 v01 = __ldg(dl + b00 + D);
        float4 v10 = __ldg(dl + b00 + D * D);
        float4 v11 = __ldg(dl + b00 + D * D + D);

        u64 fz0 = pk2(mfz), fz1 = pk2(frz);
        u64 f01 = 0, ax = 0, ay = 0, az = 0;

        // (ox,oy) = (0,0)
        {
            u64 t0 = pk(v00.x, v00.y), t1 = pk(v00.z, v00.w);
            u64 s = fma2(t0, fz0, mul2(t1, fz1));
            u64 d = add2(t1, neg2(t0));
            float wxy = mfx * mfy;
            f01 = fma2(pk2(wxy), s, f01);
            ax  = fma2(pk2(-mfy), s, ax);
            ay  = fma2(pk2(-mfx), s, ay);
            az  = fma2(pk2(wxy), d, az);
        }
        // (0,1)
        {
            u64 t0 = pk(v01.x, v01.y), t1 = pk(v01.z, v01.w);
            u64 s = fma2(t0, fz0, mul2(t1, fz1));
            u64 d = add2(t1, neg2(t0));
            float wxy = mfx * fry;
            f01 = fma2(pk2(wxy), s, f01);
            ax  = fma2(pk2(-fry), s, ax);
            ay  = fma2(pk2( mfx), s, ay);
            az  = fma2(pk2(wxy), d, az);
        }
        // (1,0)
        {
            u64 t0 = pk(v10.x, v10.y), t1 = pk(v10.z, v10.w);
            u64 s = fma2(t0, fz0, mul2(t1, fz1));
            u64 d = add2(t1, neg2(t0));
            float wxy = frx * mfy;
            f01 = fma2(pk2(wxy), s, f01);
            ax  = fma2(pk2( mfy), s, ax);
            ay  = fma2(pk2(-frx), s, ay);
            az  = fma2(pk2(wxy), d, az);
        }
        // (1,1)
        {
            u64 t0 = pk(v11.x, v11.y), t1 = pk(v11.z, v11.w);
            u64 s = fma2(t0, fz0, mul2(t1, fz1));
            u64 d = add2(t1, neg2(t0));
            float wxy = frx * fry;
            f01 = fma2(pk2(wxy), s, f01);
            ax  = fma2(pk2( fry), s, ax);
            ay  = fma2(pk2( frx), s, ay);
            az  = fma2(pk2(wxy), d, az);
        }

        feat2[l] = f01;
        accx[l] = ax; accy[l] = ay; accz[l] = az;
    }

    // ---- fused MLP forward + backward-prep (f32x2) ----
    u64 fea2[8];
    u64 dacc2[4];
    #pragma unroll
    for (int i = 0; i < 8; i++) fea2[i] = 0;
    #pragma unroll
    for (int l = 0; l < 4; l++) dacc2[l] = 0;

    #pragma unroll 4
    for (int j = 0; j < 64; j++) {
        float4 wa = w1f4[j * 2 + 0];
        float4 wb = w1f4[j * 2 + 1];
        u64 a0 = pk(wa.x, wa.y), a1 = pk(wa.z, wa.w);
        u64 a2 = pk(wb.x, wb.y), a3 = pk(wb.z, wb.w);

        u64 s = fma2(feat2[0], a0,
                fma2(feat2[1], a1,
                fma2(feat2[2], a2,
                mul2(feat2[3], a3))));
        float2 sp = upk(s);
        float hj = sp.x + sp.y;
        float hp = fmaxf(hj, 0.0f);
        u64 hp2 = pk2(hp);

        float4 c0 = w2f4[j * 4 + 0];
        float4 c1 = w2f4[j * 4 + 1];
        float4 c2 = w2f4[j * 4 + 2];
        float4 c3 = w2f4[j * 4 + 3];
        fea2[0] = fma2(hp2, pk(c0.x, c0.y), fea2[0]);
        fea2[1] = fma2(hp2, pk(c0.z, c0.w), fea2[1]);
        fea2[2] = fma2(hp2, pk(c1.x, c1.y), fea2[2]);
        fea2[3] = fma2(hp2, pk(c1.z, c1.w), fea2[3]);
        fea2[4] = fma2(hp2, pk(c2.x, c2.y), fea2[4]);
        fea2[5] = fma2(hp2, pk(c2.z, c2.w), fea2[5]);
        fea2[6] = fma2(hp2, pk(c3.x, c3.y), fea2[6]);
        fea2[7] = fma2(hp2, pk(c3.z, c3.w), fea2[7]);

        float cm = (hj > 0.0f) ? c0.x : 0.0f;
        u64 cm2 = pk2(cm);
        dacc2[0] = fma2(cm2, a0, dacc2[0]);
        dacc2[1] = fma2(cm2, a1, dacc2[1]);
        dacc2[2] = fma2(cm2, a2, dacc2[2]);
        dacc2[3] = fma2(cm2, a3, dacc2[3]);
    }

    float2 fea01 = upk(fea2[0]);
    float pre   = fea01.x + DENSITY_BIAS;
    float sigma = expf(pre);
    float g     = expf(fminf(pre, CLAMP_MAX));

    float gx = 0.0f, gy = 0.0f, gz = 0.0f;
    #pragma unroll
    for (int l = 0; l < 4; l++) {
        float2 px = upk(mul2(dacc2[l], accx[l]));
        float2 py = upk(mul2(dacc2[l], accy[l]));
        float2 pz = upk(mul2(dacc2[l], accz[l]));
        gx = fmaf(RES[l], px.x + px.y, gx);
        gy = fmaf(RES[l], py.x + py.y, gy);
        gz = fmaf(RES[l], pz.x + pz.y, gz);
    }
    gx *= g; gy *= g; gz *= g;

    float nrm = sqrtf(fmaf(gx, gx, fmaf(gy, gy, gz * gz)));
    float inv = 1.0f / nrm;

    if (active) out[pid] = sigma;

    const int npts = min(128, n - blockIdx.x * 128);

    {
        float2 f0 = upk(fea2[0]), f1 = upk(fea2[1]);
        float2 f2 = upk(fea2[2]), f3 = upk(fea2[3]);
        float2 f4 = upk(fea2[4]), f5 = upk(fea2[5]);
        float2 f6 = upk(fea2[6]), f7 = upk(fea2[7]);
        stage[tid * 4 + 0] = make_float4(f0.x, f0.y, f1.x, f1.y);
        stage[tid * 4 + 1] = make_float4(f2.x, f2.y, f3.x, f3.y);
        stage[tid * 4 + 2] = make_float4(f4.x, f4.y, f5.x, f5.y);
        stage[tid * 4 + 3] = make_float4(f6.x, f6.y, f7.x, f7.y);
    }
    __syncthreads();
    {
        float4* dst = (float4*)(out + (size_t)n) + (size_t)blockIdx.x * 512;
        int lim = npts * 4;
        for (int i = tid; i < lim; i += 128) dst[i] = stage[i];
    }
    __syncthreads();

    sf[tid * 6 + 0] = gx * inv;
    sf[tid * 6 + 1] = gy * inv;
    sf[tid * 6 + 2] = gz * inv;
    sf[tid * 6 + 3] = gx;
    sf[tid * 6 + 4] = gy;
    sf[tid * 6 + 5] = gz;
    __syncthreads();
    {
        float* ndst = out + (size_t)n * 17 + (size_t)blockIdx.x * 384;
        float* gdst = out + (size_t)n * 20 + (size_t)blockIdx.x * 384;
        int lim = npts * 3;
        for (int i = tid; i < lim; i += 128) {
            int p = i / 3, c = i - p * 3;
            ndst[i] = sf[p * 6 + c];
        }
        for (int i = tid; i < lim; i += 128) {
            int p = i / 3, c = i - p * 3;
            gdst[i] = sf[p * 6 + 3 + c];
        }
    }
}

extern "C" void kernel_launch(void* const* d_in, const int* in_sizes, int n_in,
                              void* d_out, int out_size)
{
    const float* pts   = (const float*)d_in[0];
    const float* table = (const float*)d_in[1];
    const float* W1    = (const float*)d_in[2];
    const float* W2    = (const float*)d_in[3];
    float* out = (float*)d_out;
    int n = in_sizes[0] / 3;

    build_dense_kernel<<<(NDENSE + 255) / 256, 256>>>(table);
    nerf_fused_kernel<<<(n + 127) / 128, 128>>>(pts, W1, W2, out, n);
}